// round 12
// baseline (speedup 1.0000x reference)
#include <cuda_runtime.h>
#include <cuda_bf16.h>
#include <math.h>

// Problem constants
#define TT   256
#define BB   64
#define IDIM 1024
#define HDIM 1024
#define N4   4096            // 4*HDIM, gate-major: col n = g*1024 + h
#define K2   2048            // fused K: [0,1024)=input dim, [1024,2048)=hidden dim

// ---------------- device scratch (static; allocations are banned) -------------
// g_W rows 0..1023   : masked W_x^T  (g_W[k][g*1024+h] = W_x[g][h][k]*mask)
// g_W rows 1024..2047: masked W_h^T
__device__ float g_W[K2 * N4];      // 32 MB
__device__ float g_C[BB * HDIM];    // cell state (updated in place)

// ---------- masked transpose: g_W[row_off+k][g*1024+h] = W[g][h][k]*M[g][h][k] --
__global__ void masked_transpose_kernel(const float* __restrict__ W,
                                        const float* __restrict__ Mk,
                                        int row_off)
{
    __shared__ float tile[32][33];
    const int g  = blockIdx.z;
    const int h0 = blockIdx.y * 32;
    const int k0 = blockIdx.x * 32;
    const int tx = threadIdx.x;   // 32
    const int ty = threadIdx.y;   // 8

    #pragma unroll
    for (int j = 0; j < 32; j += 8) {
        int idx = (g * HDIM + h0 + ty + j) * 1024 + k0 + tx;  // < 4.2M, fits int
        tile[ty + j][tx] = W[idx] * Mk[idx];
    }
    __syncthreads();
    #pragma unroll
    for (int j = 0; j < 32; j += 8) {
        int k = k0 + ty + j;
        int h = h0 + tx;
        g_W[(row_off + k) * N4 + g * HDIM + h] = tile[tx][ty + j];
    }
}

// ---------------- init cell state from C0 ------------------------------------
__global__ void init_c_kernel(const float* __restrict__ C0)
{
    int i = (blockIdx.x * blockDim.x + threadIdx.x) * 4;  // 64*256*4 = 65536
    float4 v = *(const float4*)&C0[i];
    *(float4*)&g_C[i] = v;
}

// ---------------- fused recurrent step ----------------------------------------
// One launch per t. grid = 128 CTAs (8 h-columns each -> 32 gate-cols),
// block = 256 threads. Each thread: 2 batch rows x 4 cols, K loop over 2048
// (first 1024 from X_t, second 1024 from H_prev). Per k: LDS.64 + LDS.128
// feeding 8 FFMA; per-SM FFMA issue = 32 cyc/k (binding), LDS well under cap.
#define KT 32
__global__ void __launch_bounds__(256)
lstm_step_kernel(const float* __restrict__ Xt,      // [64][1024]
                 const float* __restrict__ Hprev,   // [64][1024]
                 const float* __restrict__ bias,    // [4096] (g*1024+h)
                 float* __restrict__ Hout)          // [64][1024]
{
    __shared__ float Hs[KT][64];     // A tile transposed: Hs[k][b]
    __shared__ float Ws[KT][32];     // 32 cols = g*8 + hh
    __shared__ float preS[64 * 32];  // pre-activations [b][g*8+hh]

    const int tid  = threadIdx.x;
    const int h0   = blockIdx.x * 8;
    const int cg   = tid & 7;        // col group: cols cg*4 .. cg*4+3
    const int bblk = tid >> 3;       // 0..31 : b = bblk*2, bblk*2+1

    float acc[2][4];
    #pragma unroll
    for (int i = 0; i < 2; i++)
        #pragma unroll
        for (int j = 0; j < 4; j++) acc[i][j] = 0.f;

    // A-tile load indices (8 floats per thread: 64 b x 32 k total)
    const int la_b  = tid >> 2;          // 0..63
    const int la_kq = (tid & 3) * 8;     // 0,8,16,24
    // W-tile load indices (float4 per thread: 32 k x 32 cols)
    const int lw_k  = tid >> 3;          // 0..31
    const int lw_c  = (tid & 7) * 4;     // 0..28
    const int lw_g  = lw_c >> 3;         // gate
    const int lw_hh = lw_c & 7;          // h within tile

    for (int k0 = 0; k0 < K2; k0 += KT) {
        const float* Ab = (k0 < IDIM) ? Xt : Hprev;
        const int koff  = k0 & (IDIM - 1);

        // load A tile transposed
        {
            const float* ap = &Ab[la_b * IDIM + koff + la_kq];
            float4 v0 = *(const float4*)&ap[0];
            float4 v1 = *(const float4*)&ap[4];
            Hs[la_kq + 0][la_b] = v0.x; Hs[la_kq + 1][la_b] = v0.y;
            Hs[la_kq + 2][la_b] = v0.z; Hs[la_kq + 3][la_b] = v0.w;
            Hs[la_kq + 4][la_b] = v1.x; Hs[la_kq + 5][la_b] = v1.y;
            Hs[la_kq + 6][la_b] = v1.z; Hs[la_kq + 7][la_b] = v1.w;
        }
        // load W tile
        {
            float4 w = *(const float4*)&g_W[(k0 + lw_k) * N4 + lw_g * HDIM + h0 + lw_hh];
            *(float4*)&Ws[lw_k][lw_c] = w;
        }
        __syncthreads();

        #pragma unroll 8
        for (int kk = 0; kk < KT; kk++) {
            float2 hv = *(const float2*)&Hs[kk][bblk * 2];
            float4 wv = *(const float4*)&Ws[kk][cg * 4];
            acc[0][0] += hv.x * wv.x; acc[0][1] += hv.x * wv.y;
            acc[0][2] += hv.x * wv.z; acc[0][3] += hv.x * wv.w;
            acc[1][0] += hv.y * wv.x; acc[1][1] += hv.y * wv.y;
            acc[1][2] += hv.y * wv.z; acc[1][3] += hv.y * wv.w;
        }
        __syncthreads();
    }

    // stage pre-activations: col c = cg*4+j = g*8+hh
    #pragma unroll
    for (int i = 0; i < 2; i++) {
        int b = bblk * 2 + i;
        #pragma unroll
        for (int j = 0; j < 4; j++)
            preS[b * 32 + cg * 4 + j] = acc[i][j];
    }
    __syncthreads();

    // epilogue: 512 (b,hh) cells / 256 threads = 2 each
    #pragma unroll
    for (int it = 0; it < 2; it++) {
        int idx = tid + it * 256;            // 0..511
        int b   = idx >> 3;
        int hh  = idx & 7;
        int hg  = h0 + hh;
        float pi = preS[b * 32 +  0 + hh] + bias[0 * HDIM + hg];
        float pf = preS[b * 32 +  8 + hh] + bias[1 * HDIM + hg];
        float po = preS[b * 32 + 16 + hh] + bias[2 * HDIM + hg];
        float pc = preS[b * 32 + 24 + hh] + bias[3 * HDIM + hg];

        float ig = 1.f / (1.f + expf(-pi));
        float fg = 1.f / (1.f + expf(-pf));
        float og = 1.f / (1.f + expf(-po));
        float ct = tanhf(pc);

        float cold = g_C[b * HDIM + hg];
        float cnew = fg * cold + ig * ct;
        g_C[b * HDIM + hg]  = cnew;
        Hout[b * HDIM + hg] = og * tanhf(cnew);
    }
}

// ------------------------------- launch ---------------------------------------
extern "C" void kernel_launch(void* const* d_in, const int* in_sizes, int n_in,
                              void* d_out, int out_size)
{
    // Resolve inputs by element count (robust to metadata ordering):
    //   16777216 -> inputs (T,B,I)        4096 -> bias (4,H)
    //   4194304 x4 -> {W_x,W_h,mask_x,mask_h}   65536 x2 -> {H0,C0}
    const float* inputs = nullptr;
    const float* bias   = nullptr;
    const float* bigs[4] = {nullptr, nullptr, nullptr, nullptr};
    const float* sml[2]  = {nullptr, nullptr};
    int nb = 0, ns = 0, inputs_idx = -1;

    for (int i = 0; i < n_in; i++) {
        const float* p = (const float*)d_in[i];
        switch (in_sizes[i]) {
            case TT * BB * IDIM:  inputs = p; inputs_idx = i; break;
            case 4 * HDIM:        bias = p; break;
            case 4 * HDIM * IDIM: if (nb < 4) bigs[nb++] = p; break;
            case BB * HDIM:       if (ns < 2) sml[ns++] = p; break;
            default: break;
        }
    }

    const float *W_x, *W_h, *mask_x, *mask_h, *H0, *C0;
    if (inputs && bias && nb == 4 && ns == 2) {
        // Both insertion order and alphabetical order keep W's before masks and
        // preserve (i-th W <-> i-th mask) pairing. x-vs-h assignment: if inputs
        // is d_in[0] we are in setup_inputs() insertion order (W_x first);
        // otherwise assume alphabetical (W_h first).
        if (inputs_idx == 0) { W_x = bigs[0]; W_h = bigs[1]; mask_x = bigs[2]; mask_h = bigs[3]; }
        else                 { W_h = bigs[0]; W_x = bigs[1]; mask_h = bigs[2]; mask_x = bigs[3]; }
        H0 = sml[0]; C0 = sml[1];
    } else {
        // positional fallback (setup_inputs() dict order)
        inputs = (const float*)d_in[0];
        W_x    = (const float*)d_in[1];
        W_h    = (const float*)d_in[2];
        bias   = (const float*)d_in[3];
        mask_x = (const float*)d_in[4];
        mask_h = (const float*)d_in[5];
        H0     = (const float*)d_in[6];
        C0     = (const float*)d_in[7];
    }

    float* out = (float*)d_out;                   // (T,B,H)

    // 1) masked transposed weights into combined g_W
    dim3 tgrid(32, 32, 4), tblk(32, 8);
    masked_transpose_kernel<<<tgrid, tblk>>>(W_x, mask_x, 0);
    masked_transpose_kernel<<<tgrid, tblk>>>(W_h, mask_h, IDIM);

    // 2) reset cell state
    init_c_kernel<<<64, 256>>>(C0);

    // 3) sequential recurrence (x-projection fused into each step)
    for (int t = 0; t < TT; t++) {
        const float* Xt    = inputs + (size_t)t * BB * IDIM;
        const float* Hprev = (t == 0) ? H0 : (out + (size_t)(t - 1) * BB * HDIM);
        lstm_step_kernel<<<128, 256>>>(Xt, Hprev, bias,
                                       out + (size_t)t * BB * HDIM);
    }
}

// round 13
// speedup vs baseline: 1.0037x; 1.0037x over previous
#include <cuda_runtime.h>
#include <cuda_bf16.h>
#include <math.h>

// Problem constants
#define TT   256
#define BB   64
#define IDIM 1024
#define HDIM 1024
#define N4   4096            // 4*HDIM, gate-major: col n = g*1024 + h
#define K2   2048            // fused K: [0,1024)=input dim, [1024,2048)=hidden dim

// ---------------- device scratch (static; allocations are banned) -------------
// g_W rows 0..1023   : masked W_x^T  (g_W[k][g*1024+h] = W_x[g][h][k]*mask)
// g_W rows 1024..2047: masked W_h^T
__device__ float g_W[K2 * N4];      // 32 MB
__device__ float g_C[BB * HDIM];    // cell state (updated in place)

// ---------- masked transpose: g_W[row_off+k][g*1024+h] = W[g][h][k]*M[g][h][k] --
__global__ void masked_transpose_kernel(const float* __restrict__ W,
                                        const float* __restrict__ Mk,
                                        int row_off)
{
    __shared__ float tile[32][33];
    const int g  = blockIdx.z;
    const int h0 = blockIdx.y * 32;
    const int k0 = blockIdx.x * 32;
    const int tx = threadIdx.x;   // 32
    const int ty = threadIdx.y;   // 8

    #pragma unroll
    for (int j = 0; j < 32; j += 8) {
        int idx = (g * HDIM + h0 + ty + j) * 1024 + k0 + tx;  // < 4.2M, fits int
        tile[ty + j][tx] = W[idx] * Mk[idx];
    }
    __syncthreads();
    #pragma unroll
    for (int j = 0; j < 32; j += 8) {
        int k = k0 + ty + j;
        int h = h0 + tx;
        g_W[(row_off + k) * N4 + g * HDIM + h] = tile[tx][ty + j];
    }
}

// ---------------- init cell state from C0 ------------------------------------
__global__ void init_c_kernel(const float* __restrict__ C0)
{
    int i = (blockIdx.x * blockDim.x + threadIdx.x) * 4;  // 64*256*4 = 65536
    float4 v = *(const float4*)&C0[i];
    *(float4*)&g_C[i] = v;
}

// ---------------- fused recurrent step ----------------------------------------
// One launch per t. grid = 128 CTAs (8 h-columns each -> 32 gate-cols),
// block = 256 threads. Each thread: 2 batch rows x 4 cols, K loop over 2048
// (first 1024 from X_t, second 1024 from H_prev). Per k: LDS.64 + LDS.128
// feeding 8 FFMA; per-SM FFMA issue = 32 cyc/k (binding), LDS well under cap.
#define KT 32
__global__ void __launch_bounds__(256)
lstm_step_kernel(const float* __restrict__ Xt,      // [64][1024]
                 const float* __restrict__ Hprev,   // [64][1024]
                 const float* __restrict__ bias,    // [4096] (g*1024+h)
                 float* __restrict__ Hout)          // [64][1024]
{
    __shared__ float Hs[KT][64];     // A tile transposed: Hs[k][b]
    __shared__ float Ws[KT][32];     // 32 cols = g*8 + hh
    __shared__ float preS[64 * 32];  // pre-activations [b][g*8+hh]

    const int tid  = threadIdx.x;
    const int h0   = blockIdx.x * 8;
    const int cg   = tid & 7;        // col group: cols cg*4 .. cg*4+3
    const int bblk = tid >> 3;       // 0..31 : b = bblk*2, bblk*2+1

    float acc[2][4];
    #pragma unroll
    for (int i = 0; i < 2; i++)
        #pragma unroll
        for (int j = 0; j < 4; j++) acc[i][j] = 0.f;

    // A-tile load indices (8 floats per thread: 64 b x 32 k total)
    const int la_b  = tid >> 2;          // 0..63
    const int la_kq = (tid & 3) * 8;     // 0,8,16,24
    // W-tile load indices (float4 per thread: 32 k x 32 cols)
    const int lw_k  = tid >> 3;          // 0..31
    const int lw_c  = (tid & 7) * 4;     // 0..28
    const int lw_g  = lw_c >> 3;         // gate
    const int lw_hh = lw_c & 7;          // h within tile

    for (int k0 = 0; k0 < K2; k0 += KT) {
        const float* Ab = (k0 < IDIM) ? Xt : Hprev;
        const int koff  = k0 & (IDIM - 1);

        // load A tile transposed
        {
            const float* ap = &Ab[la_b * IDIM + koff + la_kq];
            float4 v0 = *(const float4*)&ap[0];
            float4 v1 = *(const float4*)&ap[4];
            Hs[la_kq + 0][la_b] = v0.x; Hs[la_kq + 1][la_b] = v0.y;
            Hs[la_kq + 2][la_b] = v0.z; Hs[la_kq + 3][la_b] = v0.w;
            Hs[la_kq + 4][la_b] = v1.x; Hs[la_kq + 5][la_b] = v1.y;
            Hs[la_kq + 6][la_b] = v1.z; Hs[la_kq + 7][la_b] = v1.w;
        }
        // load W tile
        {
            float4 w = *(const float4*)&g_W[(k0 + lw_k) * N4 + lw_g * HDIM + h0 + lw_hh];
            *(float4*)&Ws[lw_k][lw_c] = w;
        }
        __syncthreads();

        #pragma unroll 8
        for (int kk = 0; kk < KT; kk++) {
            float2 hv = *(const float2*)&Hs[kk][bblk * 2];
            float4 wv = *(const float4*)&Ws[kk][cg * 4];
            acc[0][0] += hv.x * wv.x; acc[0][1] += hv.x * wv.y;
            acc[0][2] += hv.x * wv.z; acc[0][3] += hv.x * wv.w;
            acc[1][0] += hv.y * wv.x; acc[1][1] += hv.y * wv.y;
            acc[1][2] += hv.y * wv.z; acc[1][3] += hv.y * wv.w;
        }
        __syncthreads();
    }

    // stage pre-activations: col c = cg*4+j = g*8+hh
    #pragma unroll
    for (int i = 0; i < 2; i++) {
        int b = bblk * 2 + i;
        #pragma unroll
        for (int j = 0; j < 4; j++)
            preS[b * 32 + cg * 4 + j] = acc[i][j];
    }
    __syncthreads();

    // epilogue: 512 (b,hh) cells / 256 threads = 2 each
    #pragma unroll
    for (int it = 0; it < 2; it++) {
        int idx = tid + it * 256;            // 0..511
        int b   = idx >> 3;
        int hh  = idx & 7;
        int hg  = h0 + hh;
        float pi = preS[b * 32 +  0 + hh] + bias[0 * HDIM + hg];
        float pf = preS[b * 32 +  8 + hh] + bias[1 * HDIM + hg];
        float po = preS[b * 32 + 16 + hh] + bias[2 * HDIM + hg];
        float pc = preS[b * 32 + 24 + hh] + bias[3 * HDIM + hg];

        float ig = 1.f / (1.f + expf(-pi));
        float fg = 1.f / (1.f + expf(-pf));
        float og = 1.f / (1.f + expf(-po));
        float ct = tanhf(pc);

        float cold = g_C[b * HDIM + hg];
        float cnew = fg * cold + ig * ct;
        g_C[b * HDIM + hg]  = cnew;
        Hout[b * HDIM + hg] = og * tanhf(cnew);
    }
}

// ------------------------------- launch ---------------------------------------
extern "C" void kernel_launch(void* const* d_in, const int* in_sizes, int n_in,
                              void* d_out, int out_size)
{
    // Resolve inputs by element count (robust to metadata ordering):
    //   16777216 -> inputs (T,B,I)        4096 -> bias (4,H)
    //   4194304 x4 -> {W_x,W_h,mask_x,mask_h}   65536 x2 -> {H0,C0}
    const float* inputs = nullptr;
    const float* bias   = nullptr;
    const float* bigs[4] = {nullptr, nullptr, nullptr, nullptr};
    const float* sml[2]  = {nullptr, nullptr};
    int nb = 0, ns = 0, inputs_idx = -1;

    for (int i = 0; i < n_in; i++) {
        const float* p = (const float*)d_in[i];
        switch (in_sizes[i]) {
            case TT * BB * IDIM:  inputs = p; inputs_idx = i; break;
            case 4 * HDIM:        bias = p; break;
            case 4 * HDIM * IDIM: if (nb < 4) bigs[nb++] = p; break;
            case BB * HDIM:       if (ns < 2) sml[ns++] = p; break;
            default: break;
        }
    }

    const float *W_x, *W_h, *mask_x, *mask_h, *H0, *C0;
    if (inputs && bias && nb == 4 && ns == 2) {
        // Both insertion order and alphabetical order keep W's before masks and
        // preserve (i-th W <-> i-th mask) pairing. x-vs-h assignment: if inputs
        // is d_in[0] we are in setup_inputs() insertion order (W_x first);
        // otherwise assume alphabetical (W_h first).
        if (inputs_idx == 0) { W_x = bigs[0]; W_h = bigs[1]; mask_x = bigs[2]; mask_h = bigs[3]; }
        else                 { W_h = bigs[0]; W_x = bigs[1]; mask_h = bigs[2]; mask_x = bigs[3]; }
        H0 = sml[0]; C0 = sml[1];
    } else {
        // positional fallback (setup_inputs() dict order)
        inputs = (const float*)d_in[0];
        W_x    = (const float*)d_in[1];
        W_h    = (const float*)d_in[2];
        bias   = (const float*)d_in[3];
        mask_x = (const float*)d_in[4];
        mask_h = (const float*)d_in[5];
        H0     = (const float*)d_in[6];
        C0     = (const float*)d_in[7];
    }

    float* out = (float*)d_out;                   // (T,B,H)

    // 1) masked transposed weights into combined g_W
    dim3 tgrid(32, 32, 4), tblk(32, 8);
    masked_transpose_kernel<<<tgrid, tblk>>>(W_x, mask_x, 0);
    masked_transpose_kernel<<<tgrid, tblk>>>(W_h, mask_h, IDIM);

    // 2) reset cell state
    init_c_kernel<<<64, 256>>>(C0);

    // 3) sequential recurrence (x-projection fused into each step)
    for (int t = 0; t < TT; t++) {
        const float* Xt    = inputs + (size_t)t * BB * IDIM;
        const float* Hprev = (t == 0) ? H0 : (out + (size_t)(t - 1) * BB * HDIM);
        lstm_step_kernel<<<128, 256>>>(Xt, Hprev, bias,
                                       out + (size_t)t * BB * HDIM);
    }
}

// round 15
// speedup vs baseline: 2.4137x; 2.4047x over previous
#include <cuda_runtime.h>
#include <cuda_bf16.h>
#include <math.h>

// Problem constants
#define TT   256
#define BB   64
#define IDIM 1024
#define HDIM 1024
#define N4   4096            // 4*HDIM, gate-major: col n = g*1024 + h
#define K2   2048            // fused K: [0,1024)=input dim, [1024,2048)=hidden dim

#define NSL  8               // K slices (0-3 -> X, 4-7 -> H)
#define BKS  (K2 / NSL)      // 256 k per slice
#define KT   32              // smem k-tile
#define BN   32              // n-cols per CTA

// ---------------- device scratch (static; allocations are banned) -------------
__device__ float g_W[K2 * N4];             // 32 MB masked [k][g*1024+h] weights
__device__ float g_Part[NSL * BB * N4];    // 8 MB partial pre-activations
__device__ float g_C[BB * HDIM];           // cell state

// ---------- masked transpose: g_W[row_off+k][g*1024+h] = W[g][h][k]*M[g][h][k] --
__global__ void masked_transpose_kernel(const float* __restrict__ W,
                                        const float* __restrict__ Mk,
                                        int row_off)
{
    __shared__ float tile[32][33];
    const int g  = blockIdx.z;
    const int h0 = blockIdx.y * 32;
    const int k0 = blockIdx.x * 32;
    const int tx = threadIdx.x;   // 32
    const int ty = threadIdx.y;   // 8

    #pragma unroll
    for (int j = 0; j < 32; j += 8) {
        int idx = (g * HDIM + h0 + ty + j) * 1024 + k0 + tx;
        tile[ty + j][tx] = W[idx] * Mk[idx];
    }
    __syncthreads();
    #pragma unroll
    for (int j = 0; j < 32; j += 8) {
        int k = k0 + ty + j;
        int h = h0 + tx;
        g_W[(row_off + k) * N4 + g * HDIM + h] = tile[tx][ty + j];
    }
}

// ---------------- init cell state from C0 ------------------------------------
__global__ void init_c_kernel(const float* __restrict__ C0)
{
    int i = (blockIdx.x * blockDim.x + threadIdx.x) * 4;
    float4 v = *(const float4*)&C0[i];
    *(float4*)&g_C[i] = v;
}

// ---------------- per-step K-split GEMM --------------------------------------
// grid(128, 8): x = n-tile (32 cols), y = k-slice (256 k). block = 128 threads.
// CTA tile 64b x 32n x 256k. Thread tile 4b x 4c (16 FFMA per 2 LDS.128).
// Register prefetch of next-k fragments + register-staged global tile prefetch.
__global__ void __launch_bounds__(128)
gemm_step_kernel(const float* __restrict__ Xt,      // [64][1024]
                 const float* __restrict__ Hprev)   // [64][1024]
{
    __shared__ float As[KT][BB];   // [k][b]
    __shared__ float Bs[KT][BN];   // [k][n]

    const int tid = threadIdx.x;
    const int n0  = blockIdx.x * BN;
    const int s   = blockIdx.y;

    const float* A  = (s < NSL / 2) ? Xt : Hprev;
    const int kbase = (s & (NSL / 2 - 1)) * BKS;     // k offset within source

    const int tx = tid & 7;        // n group: cols tx*4..+3
    const int ty = tid >> 3;       // b group: rows ty*4..+3 (0..15)

    // A staging: each thread 16 consecutive k of one b-row
    const int la_b = tid >> 1;            // 0..63
    const int la_k = (tid & 1) * 16;      // 0 or 16
    // B staging: each thread 8 consecutive n of one k-row
    const int lb_k = tid >> 2;            // 0..31
    const int lb_n = (tid & 3) * 8;       // 0,8,16,24

    const float* Aptr = A + la_b * IDIM + kbase + la_k;
    const float* Bptr = g_W + (size_t)(s * BKS + lb_k) * N4 + n0 + lb_n;

    float4 rA[4], rB[2];
    rA[0] = *(const float4*)(Aptr + 0);
    rA[1] = *(const float4*)(Aptr + 4);
    rA[2] = *(const float4*)(Aptr + 8);
    rA[3] = *(const float4*)(Aptr + 12);
    rB[0] = *(const float4*)(Bptr + 0);
    rB[1] = *(const float4*)(Bptr + 4);

    float acc[4][4];
    #pragma unroll
    for (int i = 0; i < 4; i++)
        #pragma unroll
        for (int j = 0; j < 4; j++) acc[i][j] = 0.f;

    for (int k0 = 0; k0 < BKS; k0 += KT) {
        // commit staged tile to smem
        #pragma unroll
        for (int i = 0; i < 4; i++) {
            As[la_k + i * 4 + 0][la_b] = rA[i].x;
            As[la_k + i * 4 + 1][la_b] = rA[i].y;
            As[la_k + i * 4 + 2][la_b] = rA[i].z;
            As[la_k + i * 4 + 3][la_b] = rA[i].w;
        }
        *(float4*)&Bs[lb_k][lb_n + 0] = rB[0];
        *(float4*)&Bs[lb_k][lb_n + 4] = rB[1];
        __syncthreads();

        // stage next tile from global (latency overlapped with compute)
        if (k0 + KT < BKS) {
            const float* ap = Aptr + k0 + KT;
            const float* bp = Bptr + (size_t)(k0 + KT) * N4;
            rA[0] = *(const float4*)(ap + 0);
            rA[1] = *(const float4*)(ap + 4);
            rA[2] = *(const float4*)(ap + 8);
            rA[3] = *(const float4*)(ap + 12);
            rB[0] = *(const float4*)(bp + 0);
            rB[1] = *(const float4*)(bp + 4);
        }

        // compute KT k's with one-step register prefetch
        float4 aC = *(const float4*)&As[0][ty * 4];
        float4 bC = *(const float4*)&Bs[0][tx * 4];
        #pragma unroll
        for (int kk = 0; kk < KT; kk++) {
            float4 aN, bN;
            if (kk + 1 < KT) {
                aN = *(const float4*)&As[kk + 1][ty * 4];
                bN = *(const float4*)&Bs[kk + 1][tx * 4];
            }
            acc[0][0] += aC.x * bC.x; acc[0][1] += aC.x * bC.y;
            acc[0][2] += aC.x * bC.z; acc[0][3] += aC.x * bC.w;
            acc[1][0] += aC.y * bC.x; acc[1][1] += aC.y * bC.y;
            acc[1][2] += aC.y * bC.z; acc[1][3] += aC.y * bC.w;
            acc[2][0] += aC.z * bC.x; acc[2][1] += aC.z * bC.y;
            acc[2][2] += aC.z * bC.z; acc[2][3] += aC.z * bC.w;
            acc[3][0] += aC.w * bC.x; acc[3][1] += aC.w * bC.y;
            acc[3][2] += aC.w * bC.z; acc[3][3] += aC.w * bC.w;
            aC = aN; bC = bN;
        }
        __syncthreads();
    }

    // write partials: g_Part[s][b][n]
    #pragma unroll
    for (int i = 0; i < 4; i++) {
        int b = ty * 4 + i;
        float* pp = &g_Part[((size_t)s * BB + b) * N4 + n0 + tx * 4];
        float4 v = make_float4(acc[i][0], acc[i][1], acc[i][2], acc[i][3]);
        *(float4*)pp = v;
    }
}

// ---------------- per-step activation / state update --------------------------
// 65536 threads: one per (b,h). Sums 8 partials per gate + bias, applies gates.
__global__ void __launch_bounds__(256)
lstm_act_kernel(const float* __restrict__ bias,
                float* __restrict__ Hout)
{
    const int idx = blockIdx.x * 256 + threadIdx.x;   // 0..65535
    const int b = idx >> 10;
    const int h = idx & 1023;

    float g[4];
    #pragma unroll
    for (int gi = 0; gi < 4; gi++) {
        float v = bias[gi * HDIM + h];
        #pragma unroll
        for (int s = 0; s < NSL; s++)
            v += g_Part[((size_t)s * BB + b) * N4 + gi * HDIM + h];
        g[gi] = v;
    }

    float ig = 1.f / (1.f + __expf(-g[0]));
    float fg = 1.f / (1.f + __expf(-g[1]));
    float og = 1.f / (1.f + __expf(-g[2]));
    float ct = tanhf(g[3]);

    float cold = g_C[idx];
    float cnew = fg * cold + ig * ct;
    g_C[idx]  = cnew;
    Hout[idx] = og * tanhf(cnew);
}

// ------------------------------- launch ---------------------------------------
extern "C" void kernel_launch(void* const* d_in, const int* in_sizes, int n_in,
                              void* d_out, int out_size)
{
    // Resolve inputs by element count (robust to metadata ordering):
    const float* inputs = nullptr;
    const float* bias   = nullptr;
    const float* bigs[4] = {nullptr, nullptr, nullptr, nullptr};
    const float* sml[2]  = {nullptr, nullptr};
    int nb = 0, ns = 0, inputs_idx = -1;

    for (int i = 0; i < n_in; i++) {
        const float* p = (const float*)d_in[i];
        switch (in_sizes[i]) {
            case TT * BB * IDIM:  inputs = p; inputs_idx = i; break;
            case 4 * HDIM:        bias = p; break;
            case 4 * HDIM * IDIM: if (nb < 4) bigs[nb++] = p; break;
            case BB * HDIM:       if (ns < 2) sml[ns++] = p; break;
            default: break;
        }
    }

    const float *W_x, *W_h, *mask_x, *mask_h, *H0, *C0;
    if (inputs && bias && nb == 4 && ns == 2) {
        if (inputs_idx == 0) { W_x = bigs[0]; W_h = bigs[1]; mask_x = bigs[2]; mask_h = bigs[3]; }
        else                 { W_h = bigs[0]; W_x = bigs[1]; mask_h = bigs[2]; mask_x = bigs[3]; }
        H0 = sml[0]; C0 = sml[1];
    } else {
        inputs = (const float*)d_in[0];
        W_x    = (const float*)d_in[1];
        W_h    = (const float*)d_in[2];
        bias   = (const float*)d_in[3];
        mask_x = (const float*)d_in[4];
        mask_h = (const float*)d_in[5];
        H0     = (const float*)d_in[6];
        C0     = (const float*)d_in[7];
    }

    float* out = (float*)d_out;                   // (T,B,H)

    // 1) masked transposed weights into combined g_W
    dim3 tgrid(32, 32, 4), tblk(32, 8);
    masked_transpose_kernel<<<tgrid, tblk>>>(W_x, mask_x, 0);
    masked_transpose_kernel<<<tgrid, tblk>>>(W_h, mask_h, IDIM);

    // 2) reset cell state
    init_c_kernel<<<64, 256>>>(C0);

    // 3) sequential recurrence: K-split GEMM + activation per step
    dim3 ggrid(N4 / BN, NSL);     // (128, 8)
    for (int t = 0; t < TT; t++) {
        const float* Xt    = inputs + (size_t)t * BB * IDIM;
        const float* Hprev = (t == 0) ? H0 : (out + (size_t)(t - 1) * BB * HDIM);
        gemm_step_kernel<<<ggrid, 128>>>(Xt, Hprev);
        lstm_act_kernel<<<256, 256>>>(bias, out + (size_t)t * BB * HDIM);
    }
}